// round 16
// baseline (speedup 1.0000x reference)
#include <cuda_runtime.h>
#include <cuda_fp16.h>

//
// Morphological skeleton — merged erode+dilate, one smem pass per iteration,
// fp16 data plane (selections are exact over the once-quantized field),
// fp32 accumulator.
// R15 vs R14 (436us):
//  - 153-row buffer (row 152 loader-filled, never stored; stale values there
//    are previous iterates => min-safe) kills the per-row index clamp and
//    enables pointer strength reduction,
//  - neighbor loads are address-selected (per-thread constant offsets) so
//    region-edge replication costs zero per-row ALU,
//  - raw loads of the next row issue before the current row's compute/store
//    (software prefetch across the unrolled ring).
// Border ring fix-up pass retained (R13 proved it is load-bearing).
//
//   skel = sum_{j=0..K-1} x_j  -  sum_{j=1..K} dilate3(x_j),  x_{j+1} = erode3(x_j)
//

#define IMG    1024
#define NIMG   16
#define TILE   128
#define HALO   12
#define RW     152                 /* valid cols / stored rows            */
#define NROW   153                 /* allocated rows (extra read-only row)*/
#define RWP    164                 /* row stride in halves                */
#define NCOL   38                  /* 4-px blocks per row (4*38 = 152)    */
#define NSTR   19
#define NT     (NCOL*NSTR)         /* 722 threads ~ 22.6 warps            */
#define RPS    8                   /* rows per strip: 19*8 = 152 exactly  */
#define BUFH   (NROW*RWP)          /* halves per buffer                   */
#define SMEMB  (2*BUFH*2)          /* 100368 bytes                        */

__device__ __half g_scratch[(size_t)NIMG * IMG * IMG];

struct Raw { __half2 c0, c1; __half l, r; };

__device__ __forceinline__ Raw ldraw(const __half* __restrict__ p, int offl, int offr)
{
    Raw t;
    const uint2 u = *(const uint2*)p;           // 8B-aligned (xb % 4 == 0)
    t.c0 = *reinterpret_cast<const __half2*>(&u.x);
    t.c1 = *reinterpret_cast<const __half2*>(&u.y);
    t.l = p[offl];                              // offl/offr encode replicate
    t.r = p[offr];
    return t;
}

struct MM { __half2 mn0, mn1, mx0, mx1, c0, c1; };

__device__ __forceinline__ MM pack(const Raw& t, bool doMn, bool doMx)
{
    MM o;
    const __half2 sl  = __halves2half2(t.l, __low2half(t.c0));              // [x-1,x0]
    const __half2 mid = __halves2half2(__high2half(t.c0), __low2half(t.c1)); // [x1,x2]
    const __half2 sr  = __halves2half2(__high2half(t.c1), t.r);             // [x3,x+4]
    o.c0 = t.c0; o.c1 = t.c1;
    if (doMn) {
        o.mn0 = __hmin2(__hmin2(sl, t.c0), mid);
        o.mn1 = __hmin2(__hmin2(mid, t.c1), sr);
    }
    if (doMx) {
        o.mx0 = __hmax2(__hmax2(sl, t.c0), mid);
        o.mx1 = __hmax2(__hmax2(mid, t.c1), sr);
    }
    return o;
}

__global__ void __launch_bounds__(NT, 1)
skel_h_kernel(const float* __restrict__ xin,       // fp32 input (launch 1)
              const __half* __restrict__ hin,      // fp16 input (launch 2)
              __half* __restrict__ xout,           // fp16 x_K out
              float* __restrict__ skel,
              int K, int accum, int writex, int halfin)
{
    extern __shared__ __half smem[];
    __half* cur = smem;            // x_p
    __half* nxt = smem + BUFH;     // receives x_{p+1}

    const int tid = threadIdx.x;
    const int bx = blockIdx.x, by = blockIdx.y, bz = blockIdx.z;
    const int gx0 = bx * TILE - HALO;
    const int gy0 = by * TILE - HALO;

    // ---- load 153 rows with replicate clamp (row 152 read-only thereafter) ----
    if (halfin) {
        const __half* img = hin + (size_t)bz * IMG * IMG;
        for (int i = tid; i < NROW * RW; i += NT) {
            int y = i / RW;
            int x = i - y * RW;
            int gy = min(max(gy0 + y, 0), IMG - 1);
            int gx = min(max(gx0 + x, 0), IMG - 1);
            cur[y * RWP + x] = img[(size_t)gy * IMG + gx];
        }
    } else {
        const float* img = xin + (size_t)bz * IMG * IMG;
        for (int i = tid; i < NROW * RW; i += NT) {
            int y = i / RW;
            int x = i - y * RW;
            int gy = min(max(gy0 + y, 0), IMG - 1);
            int gx = min(max(gx0 + x, 0), IMG - 1);
            cur[y * RWP + x] = __float2half_rn(img[(size_t)gy * IMG + gx]);
        }
    }
    __syncthreads();

    const bool topE   = (by == 0);
    const bool botE   = (by == (int)gridDim.y - 1);
    const bool leftE  = (bx == 0);
    const bool rightE = (bx == (int)gridDim.x - 1);
    const bool anyE   = topE || botE || leftE || rightE;

    const int c  = tid % NCOL;                   // block column 0..37
    const int s  = tid / NCOL;                   // strip 0..18
    const int xb = c * 4;                        // 0..148 (half index)
    const bool dcol = (xb >= HALO) && (xb + 4 <= HALO + TILE);  // interior cols
    const int y0 = s * RPS;
    const int offl = (c > 0)        ? -1 : 0;    // address-selected replicate
    const int offr = (c < NCOL - 1) ?  4 : 3;
    const int baseoff = y0 * RWP + xb;
    const int aoff = (y0 > 0) ? -RWP : 0;        // top primer clamp (strip 0)

    float4 acc[RPS];
#pragma unroll
    for (int k = 0; k < RPS; k++) acc[k] = make_float4(0.f, 0.f, 0.f, 0.f);

    for (int p = 0; p <= K; ++p) {
        const bool doE = (p < K);
        const bool doD = (p > 0);
        const bool doMx = doD && dcol;           // hmax consumed only here
        const int  m   = K - p;                  // erode validity margin
        const int  elo = doE ? (HALO - m) : HALO;
        const int  ehi = doE ? (HALO + TILE + m) : HALO;

        if (doE || doMx) {
            const __half* rp = cur + baseoff;    // row y0
            __half* wp = nxt + baseoff;
            Raw rA = ldraw(rp + aoff, offl, offr);
            Raw rB = ldraw(rp,        offl, offr);
            Raw rC = ldraw(rp + RWP,  offl, offr);
            MM A = pack(rA, doE, doMx);
            MM B = pack(rB, doE, doMx);

#pragma unroll
            for (int k = 0; k < RPS; ++k) {
                const int y = y0 + k;
                // prefetch next row's raw data before this row's compute/store
                Raw rN;
                if (k < RPS - 1) rN = ldraw(rp + 2 * RWP, offl, offr);
                MM Cm = pack(rC, doE, doMx);

                // skel terms at interior rows: += x_p (p<K), -= dilate(x_p) (p>0)
                if (dcol && y >= HALO && y < HALO + TILE) {
                    if (doMx) {
                        const __half2 d0 = __hmax2(__hmax2(A.mx0, B.mx0), Cm.mx0);
                        const __half2 d1 = __hmax2(__hmax2(A.mx1, B.mx1), Cm.mx1);
                        const float2 f0 = __half22float2(d0);
                        const float2 f1 = __half22float2(d1);
                        acc[k].x -= f0.x; acc[k].y -= f0.y;
                        acc[k].z -= f1.x; acc[k].w -= f1.y;
                    }
                    if (doE) {
                        const float2 b0 = __half22float2(B.c0);
                        const float2 b1 = __half22float2(B.c1);
                        acc[k].x += b0.x; acc[k].y += b0.y;
                        acc[k].z += b1.x; acc[k].w += b1.y;
                    }
                }
                // erode -> x_{p+1}
                if (doE && y >= elo && y < ehi) {
                    const __half2 e0 = __hmin2(__hmin2(A.mn0, B.mn0), Cm.mn0);
                    const __half2 e1 = __hmin2(__hmin2(A.mn1, B.mn1), Cm.mn1);
                    uint2 w;
                    w.x = *reinterpret_cast<const unsigned*>(&e0);
                    w.y = *reinterpret_cast<const unsigned*>(&e1);
                    *(uint2*)wp = w;
                }
                A = B; B = Cm; rC = rN;
                rp += RWP; wp += RWP;
            }
        }
        __syncthreads();

        // image-border ring fix-up on freshly eroded buffer (edge blocks only):
        // the inner halo ring must hold exact boundary replicas of e so the
        // unclipped dilate equals the clipped dilate (NOT self-maintaining).
        if (doE && anyE) {
            if (tid < TILE + 2) {
                int o = HALO - 1 + tid;                    // 11..140
                int sx = o;
                if (leftE  && sx < HALO)             sx = HALO;
                if (rightE && sx > HALO + TILE - 1)  sx = HALO + TILE - 1;
                int sy = o;
                if (topE && sy < HALO)               sy = HALO;
                if (botE && sy > HALO + TILE - 1)    sy = HALO + TILE - 1;
                if (topE)   nxt[(HALO - 1) * RWP + o]      = nxt[HALO * RWP + sx];
                if (botE)   nxt[(HALO + TILE) * RWP + o]   = nxt[(HALO + TILE - 1) * RWP + sx];
                if (leftE)  nxt[o * RWP + (HALO - 1)]      = nxt[sy * RWP + HALO];
                if (rightE) nxt[o * RWP + (HALO + TILE)]   = nxt[sy * RWP + (HALO + TILE - 1)];
            }
            __syncthreads();
        }

        if (doE) { __half* t = cur; cur = nxt; nxt = t; }
    }

    // ---- outputs ----
    if (dcol) {
        float* so = skel + (size_t)bz * IMG * IMG;
        __half* xo = xout + (size_t)bz * IMG * IMG;
#pragma unroll
        for (int k = 0; k < RPS; k++) {
            const int y = y0 + k;
            if (y >= HALO && y < HALO + TILE) {
                const size_t off = (size_t)(by * TILE + (y - HALO)) * IMG
                                 + (size_t)(bx * TILE + (xb - HALO));
                if (writex)
                    *(uint2*)(xo + off) = *(const uint2*)(cur + y * RWP + xb);
                if (accum) {
                    float4 sv = *(const float4*)(so + off);
                    sv.x += acc[k].x; sv.y += acc[k].y;
                    sv.z += acc[k].z; sv.w += acc[k].w;
                    *(float4*)(so + off) = sv;
                } else {
                    *(float4*)(so + off) = acc[k];
                }
            }
        }
    }
}

extern "C" void kernel_launch(void* const* d_in, const int* in_sizes, int n_in,
                              void* d_out, int out_size)
{
    (void)in_sizes; (void)n_in; (void)out_size;
    const float* x = (const float*)d_in[0];
    float* skel = (float*)d_out;

    __half* scratch = nullptr;
    cudaGetSymbolAddress((void**)&scratch, g_scratch);

    cudaFuncSetAttribute(skel_h_kernel,
                         cudaFuncAttributeMaxDynamicSharedMemorySize, SMEMB);

    dim3 grid(IMG / TILE, IMG / TILE, NIMG);   // 8 x 8 x 16
    // iterations 0..10 (11 terms): init skel, write x_11 (fp16) to scratch
    skel_h_kernel<<<grid, NT, SMEMB>>>(x, nullptr, scratch, skel, 11, 0, 1, 0);
    // iterations 11..20 (10 terms): accumulate skel
    skel_h_kernel<<<grid, NT, SMEMB>>>(nullptr, scratch, scratch, skel, 10, 1, 0, 1);
}

// round 17
// speedup vs baseline: 1.4171x; 1.4171x over previous
#include <cuda_runtime.h>
#include <cuda_fp16.h>

//
// Morphological skeleton — merged erode+dilate, one smem pass per iteration,
// fp16 data plane (selections exact over the once-quantized field).
// R16 = R14 (436us) + two surgical changes:
//  1. interior accumulation uses one packed fp16 subtraction per pair
//     (t = x_p (-)h dilate) then converts: 10 fewer instructions per
//     interior row-block. Terms are non-negative (opening <= x), so the
//     <=2^-11 per-term rounding cannot cancel-amplify.
//  2. 153rd buffer row (loader-filled, never stored; stale row is a previous
//     iterate => min-safe) removes the per-row index clamp.
// Border ring fix-up pass retained verbatim (load-bearing, proven in R13).
//
//   skel = x_0 + sum_{p=1..K-1}(x_p - d_p) - d_K,   d_p = dilate3(x_p),
//   x_{p+1} = erode3(x_p)
//

#define IMG    1024
#define NIMG   16
#define TILE   128
#define HALO   12
#define RW     152                 /* valid cols / stored rows            */
#define NROW   153                 /* allocated rows (extra read-only)    */
#define RWP    164                 /* row stride in halves                */
#define NCOL   38                  /* 4-px blocks per row (4*38 = 152)    */
#define NSTR   19
#define NT     (NCOL*NSTR)         /* 722 threads ~ 22.6 warps            */
#define RPS    8                   /* rows per strip: 19*8 = 152 exactly  */
#define BUFH   (NROW*RWP)          /* halves per buffer                   */
#define SMEMB  (2*BUFH*2)          /* 100368 bytes                        */

__device__ __half g_scratch[(size_t)NIMG * IMG * IMG];

struct RowH {
    __half2 c0, c1;      // raw x at cols 4c..4c+3
    __half2 mn0, mn1;    // horizontal 3-min pairs
    __half2 mx0, mx1;    // horizontal 3-max pairs
};

// One row-block: LDS.64 center + 2 scalar half LDS; shifted pairs packed in
// registers (no shuffles).
__device__ __forceinline__ void rowmm(const __half* __restrict__ row, int xb,
                                      RowH& o, bool doMn, bool doMx)
{
    const uint2 u = *(const uint2*)(row + xb);          // 8B aligned (xb%4==0)
    __half2 c0 = *reinterpret_cast<const __half2*>(&u.x);
    __half2 c1 = *reinterpret_cast<const __half2*>(&u.y);
    const __half l = (xb > 0)      ? row[xb - 1] : __low2half(c0);   // replicate
    const __half r = (xb + 4 < RW) ? row[xb + 4] : __high2half(c1);  // (min-safe)
    const __half2 sl  = __halves2half2(l, __low2half(c0));              // [x-1,x0]
    const __half2 mid = __halves2half2(__high2half(c0), __low2half(c1)); // [x1,x2]
    const __half2 sr  = __halves2half2(__high2half(c1), r);             // [x3,x+4]
    o.c0 = c0; o.c1 = c1;
    if (doMn) {
        o.mn0 = __hmin2(__hmin2(sl, c0), mid);
        o.mn1 = __hmin2(__hmin2(mid, c1), sr);
    }
    if (doMx) {
        o.mx0 = __hmax2(__hmax2(sl, c0), mid);
        o.mx1 = __hmax2(__hmax2(mid, c1), sr);
    }
}

__global__ void __launch_bounds__(NT, 1)
skel_h_kernel(const float* __restrict__ xin,       // fp32 input (launch 1)
              const __half* __restrict__ hin,      // fp16 input (launch 2)
              __half* __restrict__ xout,           // fp16 x_K out
              float* __restrict__ skel,
              int K, int accum, int writex, int halfin)
{
    extern __shared__ __half smem[];
    __half* cur = smem;            // x_p
    __half* nxt = smem + BUFH;     // receives x_{p+1}

    const int tid = threadIdx.x;
    const int bx = blockIdx.x, by = blockIdx.y, bz = blockIdx.z;
    const int gx0 = bx * TILE - HALO;
    const int gy0 = by * TILE - HALO;

    // ---- load 153 rows with replicate clamp (row 152 read-only after) ----
    if (halfin) {
        const __half* img = hin + (size_t)bz * IMG * IMG;
        for (int i = tid; i < NROW * RW; i += NT) {
            int y = i / RW;
            int x = i - y * RW;
            int gy = min(max(gy0 + y, 0), IMG - 1);
            int gx = min(max(gx0 + x, 0), IMG - 1);
            cur[y * RWP + x] = img[(size_t)gy * IMG + gx];
        }
    } else {
        const float* img = xin + (size_t)bz * IMG * IMG;
        for (int i = tid; i < NROW * RW; i += NT) {
            int y = i / RW;
            int x = i - y * RW;
            int gy = min(max(gy0 + y, 0), IMG - 1);
            int gx = min(max(gx0 + x, 0), IMG - 1);
            cur[y * RWP + x] = __float2half_rn(img[(size_t)gy * IMG + gx]);
        }
    }
    __syncthreads();

    const bool topE   = (by == 0);
    const bool botE   = (by == (int)gridDim.y - 1);
    const bool leftE  = (bx == 0);
    const bool rightE = (bx == (int)gridDim.x - 1);
    const bool anyE   = topE || botE || leftE || rightE;

    const int c  = tid % NCOL;                   // block column 0..37
    const int s  = tid / NCOL;                   // strip 0..18
    const int xb = c * 4;                        // 0..148 (half index)
    const bool dcol = (xb >= HALO) && (xb + 4 <= HALO + TILE);  // interior cols
    const int y0 = s * RPS;
    const int aoff = (y0 > 0) ? -RWP : 0;        // primer clamp (strip 0 only)
    const int baseoff = y0 * RWP;

    float4 acc[RPS];
#pragma unroll
    for (int k = 0; k < RPS; k++) acc[k] = make_float4(0.f, 0.f, 0.f, 0.f);

    for (int p = 0; p <= K; ++p) {
        const bool doE = (p < K);
        const bool doD = (p > 0);
        const bool doMx = doD && dcol;           // hmax consumed only here
        const int  m   = K - p;                  // erode validity margin
        const int  elo = doE ? (HALO - m) : HALO;
        const int  ehi = doE ? (HALO + TILE + m) : HALO;

        if (doE || doMx) {
            const __half* rb = cur + baseoff;    // base of row y0
            __half* wp = nxt + baseoff + xb;
            RowH A, B, C;
            rowmm(rb + aoff, xb, A, doE, doMx);
            rowmm(rb,        xb, B, doE, doMx);

#pragma unroll
            for (int k = 0; k < RPS; ++k) {
                const int y = y0 + k;
                rowmm(rb + RWP, xb, C, doE, doMx);   // row y+1 (<= 152, valid)

                // skel terms at interior rows
                if (dcol && y >= HALO && y < HALO + TILE) {
                    if (doMx) {
                        const __half2 d0 = __hmax2(__hmax2(A.mx0, B.mx0), C.mx0);
                        const __half2 d1 = __hmax2(__hmax2(A.mx1, B.mx1), C.mx1);
                        if (doE) {
                            // t = x_p - d, exact-operand fp16 subtract (t >= 0)
                            const __half2 t0 = __hsub2(B.c0, d0);
                            const __half2 t1 = __hsub2(B.c1, d1);
                            const float2 f0 = __half22float2(t0);
                            const float2 f1 = __half22float2(t1);
                            acc[k].x += f0.x; acc[k].y += f0.y;
                            acc[k].z += f1.x; acc[k].w += f1.y;
                        } else {                 // last pass: -= d only
                            const float2 f0 = __half22float2(d0);
                            const float2 f1 = __half22float2(d1);
                            acc[k].x -= f0.x; acc[k].y -= f0.y;
                            acc[k].z -= f1.x; acc[k].w -= f1.y;
                        }
                    } else if (doE) {            // p == 0: += x_0 only
                        const float2 b0 = __half22float2(B.c0);
                        const float2 b1 = __half22float2(B.c1);
                        acc[k].x += b0.x; acc[k].y += b0.y;
                        acc[k].z += b1.x; acc[k].w += b1.y;
                    }
                }
                // erode -> x_{p+1}
                if (doE && y >= elo && y < ehi) {
                    const __half2 e0 = __hmin2(__hmin2(A.mn0, B.mn0), C.mn0);
                    const __half2 e1 = __hmin2(__hmin2(A.mn1, B.mn1), C.mn1);
                    uint2 w;
                    w.x = *reinterpret_cast<const unsigned*>(&e0);
                    w.y = *reinterpret_cast<const unsigned*>(&e1);
                    *(uint2*)wp = w;
                }
                A = B; B = C;
                rb += RWP; wp += RWP;
            }
        }
        __syncthreads();

        // image-border ring fix-up on freshly eroded buffer (edge blocks only):
        // the inner halo ring must hold exact boundary replicas of e so the
        // unclipped dilate equals the clipped dilate (NOT self-maintaining).
        if (doE && anyE) {
            if (tid < TILE + 2) {
                int o = HALO - 1 + tid;                    // 11..140
                int sx = o;
                if (leftE  && sx < HALO)             sx = HALO;
                if (rightE && sx > HALO + TILE - 1)  sx = HALO + TILE - 1;
                int sy = o;
                if (topE && sy < HALO)               sy = HALO;
                if (botE && sy > HALO + TILE - 1)    sy = HALO + TILE - 1;
                if (topE)   nxt[(HALO - 1) * RWP + o]      = nxt[HALO * RWP + sx];
                if (botE)   nxt[(HALO + TILE) * RWP + o]   = nxt[(HALO + TILE - 1) * RWP + sx];
                if (leftE)  nxt[o * RWP + (HALO - 1)]      = nxt[sy * RWP + HALO];
                if (rightE) nxt[o * RWP + (HALO + TILE)]   = nxt[sy * RWP + (HALO + TILE - 1)];
            }
            __syncthreads();
        }

        if (doE) { __half* t = cur; cur = nxt; nxt = t; }
    }

    // ---- outputs ----
    if (dcol) {
        float* so = skel + (size_t)bz * IMG * IMG;
        __half* xo = xout + (size_t)bz * IMG * IMG;
#pragma unroll
        for (int k = 0; k < RPS; k++) {
            const int y = y0 + k;
            if (y >= HALO && y < HALO + TILE) {
                const size_t off = (size_t)(by * TILE + (y - HALO)) * IMG
                                 + (size_t)(bx * TILE + (xb - HALO));
                if (writex)
                    *(uint2*)(xo + off) = *(const uint2*)(cur + y * RWP + xb);
                if (accum) {
                    float4 sv = *(const float4*)(so + off);
                    sv.x += acc[k].x; sv.y += acc[k].y;
                    sv.z += acc[k].z; sv.w += acc[k].w;
                    *(float4*)(so + off) = sv;
                } else {
                    *(float4*)(so + off) = acc[k];
                }
            }
        }
    }
}

extern "C" void kernel_launch(void* const* d_in, const int* in_sizes, int n_in,
                              void* d_out, int out_size)
{
    (void)in_sizes; (void)n_in; (void)out_size;
    const float* x = (const float*)d_in[0];
    float* skel = (float*)d_out;

    __half* scratch = nullptr;
    cudaGetSymbolAddress((void**)&scratch, g_scratch);

    cudaFuncSetAttribute(skel_h_kernel,
                         cudaFuncAttributeMaxDynamicSharedMemorySize, SMEMB);

    dim3 grid(IMG / TILE, IMG / TILE, NIMG);   // 8 x 8 x 16
    // iterations 0..10 (11 terms): init skel, write x_11 (fp16) to scratch
    skel_h_kernel<<<grid, NT, SMEMB>>>(x, nullptr, scratch, skel, 11, 0, 1, 0);
    // iterations 11..20 (10 terms): accumulate skel
    skel_h_kernel<<<grid, NT, SMEMB>>>(nullptr, scratch, scratch, skel, 10, 1, 0, 1);
}